// round 6
// baseline (speedup 1.0000x reference)
#include <cuda_runtime.h>
#include <cuda_bf16.h>
#include <math.h>

#define DD 128           // feature dim
#define HH 16            // hidden dim
#define MAXN 131072      // >= N=100000

// Scratch for per-node projections (no cudaMalloc allowed)
__device__ float g_U[(size_t)MAXN * HH];
__device__ float g_V[(size_t)MAXN * HH];

// Kernel 1: U[n] = z[n] @ W1[0:128] + b1 ; V[n] = z[n] @ W1[128:256]
__global__ __launch_bounds__(256) void proj_kernel(
    const float* __restrict__ z, const float* __restrict__ W1,
    const float* __restrict__ b1, int N)
{
    __shared__ float sW[2 * DD * HH];   // 4096 floats = 16 KB
    __shared__ float sb[HH];
    for (int i = threadIdx.x; i < 2 * DD * HH; i += blockDim.x) sW[i] = W1[i];
    if (threadIdx.x < HH) sb[threadIdx.x] = b1[threadIdx.x];
    __syncthreads();

    int n = blockIdx.x * blockDim.x + threadIdx.x;
    if (n >= N) return;

    float u[HH], v[HH];
#pragma unroll
    for (int j = 0; j < HH; j++) { u[j] = sb[j]; v[j] = 0.0f; }

    const float4* z4 = reinterpret_cast<const float4*>(z + (size_t)n * DD);
#pragma unroll 4
    for (int kk = 0; kk < DD / 4; kk++) {
        float4 zv = z4[kk];
        float zs[4] = { zv.x, zv.y, zv.z, zv.w };
        int k = kk * 4;
#pragma unroll
        for (int t = 0; t < 4; t++) {
            const float zk = zs[t];
            const float* wu = &sW[(k + t) * HH];
            const float* wv = &sW[(DD + k + t) * HH];
#pragma unroll
            for (int j = 0; j < HH; j++) {
                u[j] = fmaf(zk, wu[j], u[j]);
                v[j] = fmaf(zk, wv[j], v[j]);
            }
        }
    }

    float4* Up = reinterpret_cast<float4*>(&g_U[(size_t)n * HH]);
    float4* Vp = reinterpret_cast<float4*>(&g_V[(size_t)n * HH]);
#pragma unroll
    for (int j = 0; j < HH / 4; j++) {
        Up[j] = make_float4(u[4*j], u[4*j+1], u[4*j+2], u[4*j+3]);
        Vp[j] = make_float4(v[4*j], v[4*j+1], v[4*j+2], v[4*j+3]);
    }
}

// Kernel 2: one warp per edge.
//   adj[e]    = dot(z[row], z[col])                 (128-dim, warp-cooperative)
//   weight[e] = softplus(relu(U[row]+V[col]) @ W2 + b2)
__global__ __launch_bounds__(256) void edge_kernel(
    const float* __restrict__ z, const int* __restrict__ ei,
    const float* __restrict__ W2, const float* __restrict__ b2,
    float* __restrict__ out, int E)
{
    int gw   = (blockIdx.x * blockDim.x + threadIdx.x) >> 5;  // global warp id == edge id
    int lane = threadIdx.x & 31;
    if (gw >= E) return;

    int r = __ldg(&ei[gw]);
    int c = __ldg(&ei[(size_t)E + gw]);

    // --- adjacency dot: each lane holds one float4 of each 128-float row ---
    const float4* zr4 = reinterpret_cast<const float4*>(z) + (size_t)r * (DD / 4);
    const float4* zc4 = reinterpret_cast<const float4*>(z) + (size_t)c * (DD / 4);
    float4 a = __ldg(&zr4[lane]);
    float4 b = __ldg(&zc4[lane]);
    float p = a.x * b.x;
    p = fmaf(a.y, b.y, p);
    p = fmaf(a.z, b.z, p);
    p = fmaf(a.w, b.w, p);

    // --- MLP head: lanes 0..15 each own one hidden unit ---
    float q = 0.0f;
    if (lane < HH) {
        float hv = g_U[(size_t)r * HH + lane] + g_V[(size_t)c * HH + lane];
        hv = fmaxf(hv, 0.0f);
        q = hv * __ldg(&W2[lane]);
    }

    // --- fused butterfly reduction of both partials ---
#pragma unroll
    for (int off = 16; off > 0; off >>= 1) {
        p += __shfl_xor_sync(0xffffffffu, p, off);
        q += __shfl_xor_sync(0xffffffffu, q, off);
    }

    if (lane == 0) {
        out[gw] = p;
        float x = q + __ldg(&b2[0]);
        // stable softplus: max(x,0) + log1p(exp(-|x|))
        out[(size_t)E + gw] = fmaxf(x, 0.0f) + log1pf(expf(-fabsf(x)));
    }
}

extern "C" void kernel_launch(void* const* d_in, const int* in_sizes, int n_in,
                              void* d_out, int out_size)
{
    const float* z  = (const float*)d_in[0];
    const int*   ei = (const int*)d_in[1];
    const float* W1 = (const float*)d_in[2];
    const float* b1 = (const float*)d_in[3];
    const float* W2 = (const float*)d_in[4];
    const float* b2 = (const float*)d_in[5];
    float*       out = (float*)d_out;

    int N = in_sizes[0] / DD;       // 100000
    int E = in_sizes[1] / 2;        // 600000

    // Kernel 1: per-node projections
    {
        int threads = 256;
        int blocks = (N + threads - 1) / threads;
        proj_kernel<<<blocks, threads>>>(z, W1, b1, N);
    }
    // Kernel 2: per-edge outputs (one warp per edge)
    {
        int threads = 256;                 // 8 warps/block
        int warps_per_block = threads / 32;
        int blocks = (E + warps_per_block - 1) / warps_per_block;
        edge_kernel<<<blocks, threads>>>(z, ei, W2, b2, out, E);
    }
}

// round 8
// speedup vs baseline: 1.7500x; 1.7500x over previous
#include <cuda_runtime.h>
#include <cuda_bf16.h>
#include <math.h>

#define DD 128           // feature dim
#define HH 16            // hidden dim
#define MAXN 131072      // >= N=100000

// Scratch for per-node projections (no cudaMalloc allowed)
__device__ float g_U[(size_t)MAXN * HH];
__device__ float g_V[(size_t)MAXN * HH];

__device__ __forceinline__ unsigned long long fma_f32x2(
    unsigned long long a, unsigned long long b, unsigned long long c)
{
    unsigned long long d;
    asm("fma.rn.f32x2 %0, %1, %2, %3;" : "=l"(d) : "l"(a), "l"(b), "l"(c));
    return d;
}

// Kernel 1: U[n] = z[n] @ W1[0:128] + b1 ; V[n] = z[n] @ W1[128:256]
// Uses Blackwell packed f32x2 FMA: 2 MACs per instruction.
__global__ __launch_bounds__(256) void proj_kernel(
    const float* __restrict__ z, const float* __restrict__ W1,
    const float* __restrict__ b1, int N)
{
    __shared__ float sWf[2 * DD * HH];   // 4096 floats = 16 KB
    __shared__ float sb[HH];
    {
        // vectorized copy: 4096 floats = 1024 float4
        const float4* src = reinterpret_cast<const float4*>(W1);
        float4* dst = reinterpret_cast<float4*>(sWf);
        for (int i = threadIdx.x; i < (2 * DD * HH) / 4; i += blockDim.x) dst[i] = src[i];
        if (threadIdx.x < HH) sb[threadIdx.x] = b1[threadIdx.x];
    }
    __syncthreads();

    int n = blockIdx.x * blockDim.x + threadIdx.x;
    if (n >= N) return;

    // accumulators as packed f32x2 (8 pairs each for u and v)
    unsigned long long u2[HH / 2], v2[HH / 2];
#pragma unroll
    for (int j = 0; j < HH / 2; j++) {
        unsigned long long bb;
        asm("mov.b64 %0, {%1, %2};" : "=l"(bb) : "f"(sb[2 * j]), "f"(sb[2 * j + 1]));
        u2[j] = bb;
        asm("mov.b64 %0, {%1, %2};" : "=l"(v2[j]) : "f"(0.0f), "f"(0.0f));
    }

    // view smem weights as 16-byte chunks of two packed pairs
    const ulonglong2* sW2 = reinterpret_cast<const ulonglong2*>(sWf);

    const float4* z4 = reinterpret_cast<const float4*>(z + (size_t)n * DD);
#pragma unroll 4
    for (int kk = 0; kk < DD / 4; kk++) {
        float4 zv = z4[kk];
        float zs[4] = { zv.x, zv.y, zv.z, zv.w };
#pragma unroll
        for (int t = 0; t < 4; t++) {
            int k = kk * 4 + t;
            unsigned long long zk2;
            asm("mov.b64 %0, {%1, %1};" : "=l"(zk2) : "f"(zs[t]));
            // row k of W1-top and W1-bottom: 16 floats = 4 ulonglong2 each
            const ulonglong2* wu = sW2 + (size_t)k * (HH / 4);
            const ulonglong2* wv = sW2 + (size_t)(DD + k) * (HH / 4);
#pragma unroll
            for (int j = 0; j < HH / 4; j++) {
                ulonglong2 a = wu[j];
                u2[2 * j]     = fma_f32x2(zk2, a.x, u2[2 * j]);
                u2[2 * j + 1] = fma_f32x2(zk2, a.y, u2[2 * j + 1]);
                ulonglong2 b = wv[j];
                v2[2 * j]     = fma_f32x2(zk2, b.x, v2[2 * j]);
                v2[2 * j + 1] = fma_f32x2(zk2, b.y, v2[2 * j + 1]);
            }
        }
    }

    ulonglong2* Up = reinterpret_cast<ulonglong2*>(&g_U[(size_t)n * HH]);
    ulonglong2* Vp = reinterpret_cast<ulonglong2*>(&g_V[(size_t)n * HH]);
#pragma unroll
    for (int j = 0; j < HH / 4; j++) {
        Up[j] = make_ulonglong2(u2[2 * j], u2[2 * j + 1]);
        Vp[j] = make_ulonglong2(v2[2 * j], v2[2 * j + 1]);
    }
}

// Kernel 2: 4 edges per warp, 8 lanes per edge.
//   adj[e]    = dot(z[row], z[col])      (128-dim, 8-lane cooperative)
//   weight[e] = softplus(relu(U[row]+V[col]) @ W2 + b2)
__global__ __launch_bounds__(256) void edge_kernel(
    const float* __restrict__ z, const int* __restrict__ ei,
    const float* __restrict__ W2, const float* __restrict__ b2,
    float* __restrict__ out, int E)
{
    int tid  = blockIdx.x * blockDim.x + threadIdx.x;
    int warp = tid >> 5;
    int lane = threadIdx.x & 31;
    int sub  = lane >> 3;       // which of 4 edges this lane serves
    int sl   = lane & 7;        // lane within the 8-lane group

    int e = warp * 4 + sub;
    if (e >= E) return;

    int r = __ldg(&ei[e]);
    int c = __ldg(&ei[(size_t)E + e]);

    // --- adjacency dot: 8 lanes cover 128 floats, 4 float4 per lane per row ---
    const float4* zr4 = reinterpret_cast<const float4*>(z) + (size_t)r * (DD / 4);
    const float4* zc4 = reinterpret_cast<const float4*>(z) + (size_t)c * (DD / 4);
    float4 a0 = __ldg(&zr4[sl]);
    float4 a1 = __ldg(&zr4[sl + 8]);
    float4 a2 = __ldg(&zr4[sl + 16]);
    float4 a3 = __ldg(&zr4[sl + 24]);
    float4 b0 = __ldg(&zc4[sl]);
    float4 b1v = __ldg(&zc4[sl + 8]);
    float4 b2v = __ldg(&zc4[sl + 16]);
    float4 b3 = __ldg(&zc4[sl + 24]);

    float p = a0.x * b0.x;
    p = fmaf(a0.y, b0.y, p);  p = fmaf(a0.z, b0.z, p);  p = fmaf(a0.w, b0.w, p);
    p = fmaf(a1.x, b1v.x, p); p = fmaf(a1.y, b1v.y, p);
    p = fmaf(a1.z, b1v.z, p); p = fmaf(a1.w, b1v.w, p);
    p = fmaf(a2.x, b2v.x, p); p = fmaf(a2.y, b2v.y, p);
    p = fmaf(a2.z, b2v.z, p); p = fmaf(a2.w, b2v.w, p);
    p = fmaf(a3.x, b3.x, p);  p = fmaf(a3.y, b3.y, p);
    p = fmaf(a3.z, b3.z, p);  p = fmaf(a3.w, b3.w, p);

    // --- MLP head: each lane owns 2 of the 16 hidden units ---
    const float2 uu = *reinterpret_cast<const float2*>(&g_U[(size_t)r * HH + 2 * sl]);
    const float2 vv = *reinterpret_cast<const float2*>(&g_V[(size_t)c * HH + 2 * sl]);
    const float2 w2 = __ldg(reinterpret_cast<const float2*>(&W2[2 * sl]));
    float h0 = fmaxf(uu.x + vv.x, 0.0f);
    float h1 = fmaxf(uu.y + vv.y, 0.0f);
    float q = fmaf(h1, w2.y, h0 * w2.x);

    // --- 3-level butterfly within each 8-lane group ---
#pragma unroll
    for (int off = 4; off > 0; off >>= 1) {
        p += __shfl_xor_sync(0xffffffffu, p, off);
        q += __shfl_xor_sync(0xffffffffu, q, off);
    }

    if (sl == 0) {
        out[e] = p;                                   // 4 consecutive lanes -> coalesced
        float x = q + __ldg(&b2[0]);
        // stable softplus: max(x,0) + log1p(exp(-|x|))
        out[(size_t)E + e] = fmaxf(x, 0.0f) + log1pf(expf(-fabsf(x)));
    }
}

extern "C" void kernel_launch(void* const* d_in, const int* in_sizes, int n_in,
                              void* d_out, int out_size)
{
    const float* z  = (const float*)d_in[0];
    const int*   ei = (const int*)d_in[1];
    const float* W1 = (const float*)d_in[2];
    const float* b1 = (const float*)d_in[3];
    const float* W2 = (const float*)d_in[4];
    const float* b2 = (const float*)d_in[5];
    float*       out = (float*)d_out;

    int N = in_sizes[0] / DD;       // 100000
    int E = in_sizes[1] / 2;        // 600000

    // Kernel 1: per-node projections
    {
        int threads = 256;
        int blocks = (N + threads - 1) / threads;
        proj_kernel<<<blocks, threads>>>(z, W1, b1, N);
    }
    // Kernel 2: per-edge outputs (4 edges per warp)
    {
        int threads = 256;                         // 8 warps = 32 edges / block
        int edges_per_block = (threads / 32) * 4;
        int blocks = (E + edges_per_block - 1) / edges_per_block;
        edge_kernel<<<blocks, threads>>>(z, ei, W2, b2, out, E);
    }
}